// round 3
// baseline (speedup 1.0000x reference)
#include <cuda_runtime.h>
#include <climits>

// Problem shape (fixed): B=4, C=1, D=64, H=256, W=256
#define SLICES      256                 // B*D
#define SPLIT       16                  // parts per slice
#define NBLOCKS     (SLICES * SPLIT)    // 4096
#define THREADS     256
#define SLICE_ELEMS 65536               // H*W
#define PART_ELEMS  (SLICE_ELEMS / SPLIT)   // 4096
#define PART_F4     (PART_ELEMS / 4)        // 1024
#define ITERS       (PART_F4 / THREADS)     // 4
#define ROWS_PER_PART 16
#define TOTAL_ELEMS 16777216.0f
#define NBOX_ELEMS  1024.0f
#define LN2F        0.69314718056f

// Scratch (no allocation allowed) — partials per block
__device__ float        g_seg[NBLOCKS];
__device__ int4         g_box[NBLOCKS];   // x=minR, y=maxR, z=minC, w=maxC
__device__ unsigned int g_count = 0;

__global__ void __launch_bounds__(THREADS, 6) fused_kernel(
    const float4* __restrict__ x4p, const float4* __restrict__ t4p,
    const float*  __restrict__ tgt, float* __restrict__ out)
{
    const int blk  = blockIdx.x;            // blk = slice*SPLIT + part
    const int tid  = threadIdx.x;
    const int part = blk & (SPLIT - 1);
    const int rowBase = part * ROWS_PER_PART;

    const float4* __restrict__ xb = x4p + (size_t)blk * PART_F4;
    const float4* __restrict__ tb = t4p + (size_t)blk * PART_F4;

    // Per-thread state. Columns are FIXED per thread: stride 256 == 0 mod 64.
    float cm0 = -1.0f, cm1 = -1.0f, cm2 = -1.0f, cm3 = -1.0f;  // per-column running max
    float accLin = 0.0f;   // sum of max(x,0) - x*t
    float accL2  = 0.0f;   // sum of log2(1 + exp(-|x|))
    unsigned rmask = 0;    // bit k: any(x>0) in this thread's k-th visited row

    #pragma unroll
    for (int k = 0; k < ITERS; ++k) {
        const int i = tid + THREADS * k;
        float4 xv = xb[i];
        float4 tv = tb[i];

        // softplus(x) - x*t, split into log2 and linear accumulators
        {
            float x = xv.x, t = tv.x;
            accLin += fmaxf(x, 0.0f);
            accLin  = __fmaf_rn(-x, t, accLin);
            accL2  += __log2f(1.0f + __expf(-fabsf(x)));
        }
        {
            float x = xv.y, t = tv.y;
            accLin += fmaxf(x, 0.0f);
            accLin  = __fmaf_rn(-x, t, accLin);
            accL2  += __log2f(1.0f + __expf(-fabsf(x)));
        }
        {
            float x = xv.z, t = tv.z;
            accLin += fmaxf(x, 0.0f);
            accLin  = __fmaf_rn(-x, t, accLin);
            accL2  += __log2f(1.0f + __expf(-fabsf(x)));
        }
        {
            float x = xv.w, t = tv.w;
            accLin += fmaxf(x, 0.0f);
            accLin  = __fmaf_rn(-x, t, accLin);
            accL2  += __log2f(1.0f + __expf(-fabsf(x)));
        }

        // column-any via running max
        cm0 = fmaxf(cm0, xv.x);
        cm1 = fmaxf(cm1, xv.y);
        cm2 = fmaxf(cm2, xv.z);
        cm3 = fmaxf(cm3, xv.w);

        // row-any for this iteration's row (compile-time bit)
        float m4 = fmaxf(fmaxf(xv.x, xv.y), fmaxf(xv.z, xv.w));
        if (m4 > 0.0f) rmask |= (1u << k);
    }

    // Decode per-thread bbox contribution
    int minR, maxR, minC, maxC;
    {
        const int rb = rowBase + (tid >> 6);   // rows visited: rb + 4k
        if (rmask) {
            minR = rb + 4 * (__ffs(rmask) - 1);
            maxR = rb + 4 * (31 - __clz(rmask));
        } else { minR = INT_MAX; maxR = -1; }

        const int cb = (tid & 63) << 2;
        unsigned cmsk = (cm0 > 0.0f ? 1u : 0u) | (cm1 > 0.0f ? 2u : 0u)
                      | (cm2 > 0.0f ? 4u : 0u) | (cm3 > 0.0f ? 8u : 0u);
        if (cmsk) {
            minC = cb + (__ffs(cmsk) - 1);
            maxC = cb + (31 - __clz(cmsk));
        } else { minC = INT_MAX; maxC = -1; }
    }

    float seg = __fmaf_rn(LN2F, accL2, accLin);

    // ---- intra-warp reduction (shuffle) ----
    #pragma unroll
    for (int off = 16; off > 0; off >>= 1) {
        seg  += __shfl_xor_sync(0xFFFFFFFFu, seg,  off);
        minR  = min(minR, __shfl_xor_sync(0xFFFFFFFFu, minR, off));
        maxR  = max(maxR, __shfl_xor_sync(0xFFFFFFFFu, maxR, off));
        minC  = min(minC, __shfl_xor_sync(0xFFFFFFFFu, minC, off));
        maxC  = max(maxC, __shfl_xor_sync(0xFFFFFFFFu, maxC, off));
    }

    // ---- cross-warp reduction via smem (8 warps) ----
    __shared__ float s_seg[8];
    __shared__ int   s_mnR[8], s_mxR[8], s_mnC[8], s_mxC[8];
    const int wid = tid >> 5, lid = tid & 31;
    if (lid == 0) {
        s_seg[wid] = seg;
        s_mnR[wid] = minR; s_mxR[wid] = maxR;
        s_mnC[wid] = minC; s_mxC[wid] = maxC;
    }
    __syncthreads();
    if (tid == 0) {
        float rs = s_seg[0];
        int rmnR = s_mnR[0], rmxR = s_mxR[0], rmnC = s_mnC[0], rmxC = s_mxC[0];
        #pragma unroll
        for (int w = 1; w < 8; ++w) {
            rs   += s_seg[w];
            rmnR  = min(rmnR, s_mnR[w]); rmxR = max(rmxR, s_mxR[w]);
            rmnC  = min(rmnC, s_mnC[w]); rmxC = max(rmxC, s_mxC[w]);
        }
        g_seg[blk] = rs;
        g_box[blk] = make_int4(rmnR, rmxR, rmnC, rmxC);
    }

    // ---- last-block-finishes tail ----
    __shared__ bool s_isLast;
    __threadfence();
    if (tid == 0) {
        unsigned int c = atomicAdd(&g_count, 1u);
        s_isLast = (c == NBLOCKS - 1);
    }
    __syncthreads();
    if (!s_isLast) return;

    // Tail: thread s handles slice s (256 threads)
    const int s = tid;
    float segT = 0.0f;
    int mnR = INT_MAX, mxR = -1, mnC = INT_MAX, mxC = -1;
    #pragma unroll
    for (int p = 0; p < SPLIT; ++p) {
        int idx = s * SPLIT + p;
        segT += __ldcg(&g_seg[idx]);
        int4 b = __ldcg(&g_box[idx]);
        mnR = min(mnR, b.x); mxR = max(mxR, b.y);
        mnC = min(mnC, b.z); mxC = max(mxC, b.w);
    }

    float bx, by, bw, bh;
    if (mxR < 0) {                       // empty mask
        bx = 0.0f; by = 0.0f; bw = 256.0f; bh = 256.0f;
    } else {
        bx = (float)mnC; by = (float)mnR;
        bw = (float)(mxC - mnC); bh = (float)(mxR - mnR);
    }

    float pred[4] = {bx, by, bw, bh};
    float l = 0.0f;
    #pragma unroll
    for (int j = 0; j < 4; ++j) {
        float d  = pred[j] - tgt[s * 4 + j];
        float ad = fabsf(d);
        l += (ad < 1.0f) ? 0.5f * d * d : ad - 0.5f;
    }

    // reduce 256 lanes: warp shuffle + smem
    #pragma unroll
    for (int off = 16; off > 0; off >>= 1) {
        segT += __shfl_xor_sync(0xFFFFFFFFu, segT, off);
        l    += __shfl_xor_sync(0xFFFFFFFFu, l,    off);
    }
    __shared__ float t_seg[8], t_box[8];
    const int wid2 = tid >> 5, lid2 = tid & 31;
    if (lid2 == 0) { t_seg[wid2] = segT; t_box[wid2] = l; }
    __syncthreads();
    if (tid == 0) {
        float fs = 0.0f, fb = 0.0f;
        #pragma unroll
        for (int w = 0; w < 8; ++w) { fs += t_seg[w]; fb += t_box[w]; }
        out[0] = fs / TOTAL_ELEMS;
        out[1] = fb / NBOX_ELEMS;
        g_count = 0;                     // reset for next graph replay
    }
}

extern "C" void kernel_launch(void* const* d_in, const int* in_sizes, int n_in,
                              void* d_out, int out_size)
{
    const float4* x4 = (const float4*)d_in[0];   // model_output
    const float4* t4 = (const float4*)d_in[1];   // target_masks
    const float*  tb = (const float*)d_in[2];    // target_bboxes
    float* out = (float*)d_out;

    fused_kernel<<<NBLOCKS, THREADS>>>(x4, t4, tb, out);
}

// round 4
// speedup vs baseline: 1.1333x; 1.1333x over previous
#include <cuda_runtime.h>
#include <climits>

// Problem shape (fixed): B=4, C=1, D=64, H=256, W=256
#define SLICES      256                 // B*D
#define SPLIT       8                   // parts per slice
#define NBLOCKS     (SLICES * SPLIT)    // 2048
#define THREADS     256
#define SLICE_ELEMS 65536               // H*W
#define PART_ELEMS  (SLICE_ELEMS / SPLIT)   // 8192
#define PART_F4     (PART_ELEMS / 4)        // 2048
#define ITERS       (PART_F4 / THREADS)     // 8
#define BATCH       4                        // float4 per load batch
#define ROWS_PER_PART 32
#define TOTAL_ELEMS 16777216.0f
#define NBOX_ELEMS  1024.0f
#define LN2F        0.6931471805599453f
#define NLOG2EF     (-1.4426950408889634f)

// Scratch (no allocation allowed) — partials per block
__device__ float        g_seg[NBLOCKS];
__device__ int4         g_box[NBLOCKS];   // x=minR, y=maxR, z=minC, w=maxC
__device__ unsigned int g_count = 0;

__global__ void __launch_bounds__(THREADS) fused_kernel(
    const float4* __restrict__ x4p, const float4* __restrict__ t4p,
    const float*  __restrict__ tgt, float* __restrict__ out)
{
    const int blk  = blockIdx.x;            // blk = slice*SPLIT + part
    const int tid  = threadIdx.x;
    const int part = blk & (SPLIT - 1);
    const int rowBase = part * ROWS_PER_PART;

    const float4* __restrict__ xb = x4p + (size_t)blk * PART_F4;
    const float4* __restrict__ tb = t4p + (size_t)blk * PART_F4;

    // Per-thread state. Columns are FIXED per thread (stride 256 ≡ 0 mod 64).
    float cm0 = -1.0f, cm1 = -1.0f, cm2 = -1.0f, cm3 = -1.0f;  // per-column running max
    float aLin0 = 0.0f, aLin1 = 0.0f;   // Σ max(x,0)
    float aT0 = 0.0f,  aT1 = 0.0f;      // Σ x·t
    float accL2 = 0.0f;                 // Σ log2(Π(1+e^-|x|))
    unsigned rmask = 0;                 // bit j: any(x>0) in j-th visited row

    #pragma unroll
    for (int b = 0; b < ITERS / BATCH; ++b) {
        float4 xr[BATCH], tr[BATCH];
        // ---- front-batched loads: 8 consecutive LDG.128 ----
        #pragma unroll
        for (int k = 0; k < BATCH; ++k)
            xr[k] = __ldcs(xb + (tid + THREADS * (BATCH * b + k)));
        #pragma unroll
        for (int k = 0; k < BATCH; ++k)
            tr[k] = __ldcs(tb + (tid + THREADS * (BATCH * b + k)));

        #pragma unroll
        for (int k = 0; k < BATCH; ++k) {
            const float4 xv = xr[k];
            const float4 tv = tr[k];

            // one LG2 per 4 elements: log2((1+e0)(1+e1)(1+e2)(1+e3))
            float e0 = __expf(-fabsf(xv.x));
            float e1 = __expf(-fabsf(xv.y));
            float e2 = __expf(-fabsf(xv.z));
            float e3 = __expf(-fabsf(xv.w));
            float p  = ((1.0f + e0) * (1.0f + e1)) * ((1.0f + e2) * (1.0f + e3));
            accL2 += __log2f(p);

            // linear terms: Σ max(x,0), Σ x·t (two chains each)
            aLin0 += fmaxf(xv.x, 0.0f);
            aLin1 += fmaxf(xv.y, 0.0f);
            aLin0 += fmaxf(xv.z, 0.0f);
            aLin1 += fmaxf(xv.w, 0.0f);
            aT0 = __fmaf_rn(xv.x, tv.x, aT0);
            aT1 = __fmaf_rn(xv.y, tv.y, aT1);
            aT0 = __fmaf_rn(xv.z, tv.z, aT0);
            aT1 = __fmaf_rn(xv.w, tv.w, aT1);

            // bbox: per-column running max + per-row any
            cm0 = fmaxf(cm0, xv.x);
            cm1 = fmaxf(cm1, xv.y);
            cm2 = fmaxf(cm2, xv.z);
            cm3 = fmaxf(cm3, xv.w);
            float m4 = fmaxf(fmaxf(xv.x, xv.y), fmaxf(xv.z, xv.w));
            if (m4 > 0.0f) rmask |= (1u << (BATCH * b + k));
        }
    }

    // Decode per-thread bbox contribution
    int minR, maxR, minC, maxC;
    {
        const int rb = rowBase + (tid >> 6);   // rows visited: rb + 4j
        if (rmask) {
            minR = rb + 4 * (__ffs(rmask) - 1);
            maxR = rb + 4 * (31 - __clz(rmask));
        } else { minR = INT_MAX; maxR = -1; }

        const int cb = (tid & 63) << 2;
        unsigned cmsk = (cm0 > 0.0f ? 1u : 0u) | (cm1 > 0.0f ? 2u : 0u)
                      | (cm2 > 0.0f ? 4u : 0u) | (cm3 > 0.0f ? 8u : 0u);
        if (cmsk) {
            minC = cb + (__ffs(cmsk) - 1);
            maxC = cb + (31 - __clz(cmsk));
        } else { minC = INT_MAX; maxC = -1; }
    }

    float seg = (aLin0 + aLin1) - (aT0 + aT1) + LN2F * accL2;

    // ---- intra-warp reduction (shuffle) ----
    #pragma unroll
    for (int off = 16; off > 0; off >>= 1) {
        seg  += __shfl_xor_sync(0xFFFFFFFFu, seg,  off);
        minR  = min(minR, __shfl_xor_sync(0xFFFFFFFFu, minR, off));
        maxR  = max(maxR, __shfl_xor_sync(0xFFFFFFFFu, maxR, off));
        minC  = min(minC, __shfl_xor_sync(0xFFFFFFFFu, minC, off));
        maxC  = max(maxC, __shfl_xor_sync(0xFFFFFFFFu, maxC, off));
    }

    // ---- cross-warp reduction via smem (8 warps) ----
    __shared__ float s_seg[8];
    __shared__ int   s_mnR[8], s_mxR[8], s_mnC[8], s_mxC[8];
    const int wid = tid >> 5, lid = tid & 31;
    if (lid == 0) {
        s_seg[wid] = seg;
        s_mnR[wid] = minR; s_mxR[wid] = maxR;
        s_mnC[wid] = minC; s_mxC[wid] = maxC;
    }
    __syncthreads();
    if (tid == 0) {
        float rs = s_seg[0];
        int rmnR = s_mnR[0], rmxR = s_mxR[0], rmnC = s_mnC[0], rmxC = s_mxC[0];
        #pragma unroll
        for (int w = 1; w < 8; ++w) {
            rs   += s_seg[w];
            rmnR  = min(rmnR, s_mnR[w]); rmxR = max(rmxR, s_mxR[w]);
            rmnC  = min(rmnC, s_mnC[w]); rmxC = max(rmxC, s_mxC[w]);
        }
        g_seg[blk] = rs;
        g_box[blk] = make_int4(rmnR, rmxR, rmnC, rmxC);
    }

    // ---- last-block-finishes tail ----
    __shared__ bool s_isLast;
    __threadfence();
    if (tid == 0) {
        unsigned int c = atomicAdd(&g_count, 1u);
        s_isLast = (c == NBLOCKS - 1);
    }
    __syncthreads();
    if (!s_isLast) return;

    // Tail: thread s handles slice s (256 threads)
    const int s = tid;
    float segT = 0.0f;
    int mnR = INT_MAX, mxR = -1, mnC = INT_MAX, mxC = -1;
    #pragma unroll
    for (int p = 0; p < SPLIT; ++p) {
        int idx = s * SPLIT + p;
        segT += __ldcg(&g_seg[idx]);
        int4 b = __ldcg(&g_box[idx]);
        mnR = min(mnR, b.x); mxR = max(mxR, b.y);
        mnC = min(mnC, b.z); mxC = max(mxC, b.w);
    }

    float bx, by, bw, bh;
    if (mxR < 0) {                       // empty mask
        bx = 0.0f; by = 0.0f; bw = 256.0f; bh = 256.0f;
    } else {
        bx = (float)mnC; by = (float)mnR;
        bw = (float)(mxC - mnC); bh = (float)(mxR - mnR);
    }

    float pred[4] = {bx, by, bw, bh};
    float l = 0.0f;
    #pragma unroll
    for (int j = 0; j < 4; ++j) {
        float d  = pred[j] - tgt[s * 4 + j];
        float ad = fabsf(d);
        l += (ad < 1.0f) ? 0.5f * d * d : ad - 0.5f;
    }

    // reduce 256 lanes: warp shuffle + smem
    #pragma unroll
    for (int off = 16; off > 0; off >>= 1) {
        segT += __shfl_xor_sync(0xFFFFFFFFu, segT, off);
        l    += __shfl_xor_sync(0xFFFFFFFFu, l,    off);
    }
    __shared__ float t_seg[8], t_box[8];
    const int wid2 = tid >> 5, lid2 = tid & 31;
    if (lid2 == 0) { t_seg[wid2] = segT; t_box[wid2] = l; }
    __syncthreads();
    if (tid == 0) {
        float fs = 0.0f, fb = 0.0f;
        #pragma unroll
        for (int w = 0; w < 8; ++w) { fs += t_seg[w]; fb += t_box[w]; }
        out[0] = fs / TOTAL_ELEMS;
        out[1] = fb / NBOX_ELEMS;
        g_count = 0;                     // reset for next graph replay
    }
}

extern "C" void kernel_launch(void* const* d_in, const int* in_sizes, int n_in,
                              void* d_out, int out_size)
{
    const float4* x4 = (const float4*)d_in[0];   // model_output
    const float4* t4 = (const float4*)d_in[1];   // target_masks
    const float*  tb = (const float*)d_in[2];    // target_bboxes
    float* out = (float*)d_out;

    fused_kernel<<<NBLOCKS, THREADS>>>(x4, t4, tb, out);
}

// round 5
// speedup vs baseline: 1.1357x; 1.0021x over previous
#include <cuda_runtime.h>
#include <climits>

// Problem shape (fixed): B=4, C=1, D=64, H=256, W=256
#define SLICES      256                 // B*D
#define SPLIT       8                   // parts per slice
#define NBLOCKS     (SLICES * SPLIT)    // 2048
#define THREADS     256
#define PART_F4     2048                // float4 per part
#define ITERS       8                   // float4 per thread
#define ROWS_PER_PART 32
#define TOTAL_ELEMS 16777216.0f
#define NBOX_ELEMS  1024.0f
#define LN2F        0.6931471805599453f

// Scratch (no allocation allowed) — partials per block
__device__ float        g_seg[NBLOCKS];
__device__ int4         g_box[NBLOCKS];   // x=minR, y=maxR, z=minC, w=maxC
__device__ unsigned int g_count = 0;

__global__ void __launch_bounds__(THREADS, 4) fused_kernel(
    const float4* __restrict__ x4p, const float4* __restrict__ t4p,
    const float*  __restrict__ tgt, float* __restrict__ out)
{
    const int blk  = blockIdx.x;            // blk = slice*SPLIT + part
    const int tid  = threadIdx.x;
    const int part = blk & (SPLIT - 1);
    const int rowBase = part * ROWS_PER_PART;

    const float4* __restrict__ xb = x4p + (size_t)blk * PART_F4 + tid;
    const float4* __restrict__ tb = t4p + (size_t)blk * PART_F4 + tid;

    // Accumulators. Columns are FIXED per thread (stride 256 ≡ 0 mod 64).
    float cm0 = -1.0f, cm1 = -1.0f, cm2 = -1.0f, cm3 = -1.0f;
    float aLin0 = 0.0f, aLin1 = 0.0f;   // Σ max(x,0)
    float aT0 = 0.0f,  aT1 = 0.0f;      // Σ x·t
    float accL2 = 0.0f;                 // Σ log2(Π(1+e^-|x|))
    unsigned rmask = 0;                 // bit k: any(x>0) in k-th visited row

    // ---- software pipeline: prefetch k+1 while computing k ----
    float4 xc = __ldcs(xb);             // current
    float4 tc = __ldcs(tb);

    #pragma unroll
    for (int k = 0; k < ITERS; ++k) {
        float4 xn, tn;
        if (k < ITERS - 1) {            // prefetch next stage
            xn = __ldcs(xb + THREADS * (k + 1));
            tn = __ldcs(tb + THREADS * (k + 1));
        }

        // ---- compute on (xc, tc) ----
        {
            const float4 xv = xc;
            const float4 tv = tc;

            // one LG2 per 4 elements: log2((1+e0)(1+e1)(1+e2)(1+e3))
            float e0 = __expf(-fabsf(xv.x));
            float e1 = __expf(-fabsf(xv.y));
            float e2 = __expf(-fabsf(xv.z));
            float e3 = __expf(-fabsf(xv.w));
            float a01 = 1.0f + e0;
            float p01 = __fmaf_rn(e1, a01, a01);       // (1+e0)(1+e1)
            float a23 = 1.0f + e2;
            float p23 = __fmaf_rn(e3, a23, a23);       // (1+e2)(1+e3)
            accL2 += __log2f(p01 * p23);

            // linear terms
            aLin0 += fmaxf(xv.x, 0.0f);
            aLin1 += fmaxf(xv.y, 0.0f);
            aLin0 += fmaxf(xv.z, 0.0f);
            aLin1 += fmaxf(xv.w, 0.0f);
            aT0 = __fmaf_rn(xv.x, tv.x, aT0);
            aT1 = __fmaf_rn(xv.y, tv.y, aT1);
            aT0 = __fmaf_rn(xv.z, tv.z, aT0);
            aT1 = __fmaf_rn(xv.w, tv.w, aT1);

            // bbox: per-column running max + per-row any
            cm0 = fmaxf(cm0, xv.x);
            cm1 = fmaxf(cm1, xv.y);
            cm2 = fmaxf(cm2, xv.z);
            cm3 = fmaxf(cm3, xv.w);
            float m4 = fmaxf(fmaxf(xv.x, xv.y), fmaxf(xv.z, xv.w));
            if (m4 > 0.0f) rmask |= (1u << k);
        }

        xc = xn;
        tc = tn;
    }

    // Decode per-thread bbox contribution
    int minR, maxR, minC, maxC;
    {
        const int rb = rowBase + (tid >> 6);   // rows visited: rb + 4k
        if (rmask) {
            minR = rb + 4 * (__ffs(rmask) - 1);
            maxR = rb + 4 * (31 - __clz(rmask));
        } else { minR = INT_MAX; maxR = -1; }

        const int cb = (tid & 63) << 2;
        unsigned cmsk = (cm0 > 0.0f ? 1u : 0u) | (cm1 > 0.0f ? 2u : 0u)
                      | (cm2 > 0.0f ? 4u : 0u) | (cm3 > 0.0f ? 8u : 0u);
        if (cmsk) {
            minC = cb + (__ffs(cmsk) - 1);
            maxC = cb + (31 - __clz(cmsk));
        } else { minC = INT_MAX; maxC = -1; }
    }

    float seg = (aLin0 + aLin1) - (aT0 + aT1) + LN2F * accL2;

    // ---- intra-warp reduction (shuffle) ----
    #pragma unroll
    for (int off = 16; off > 0; off >>= 1) {
        seg  += __shfl_xor_sync(0xFFFFFFFFu, seg,  off);
        minR  = min(minR, __shfl_xor_sync(0xFFFFFFFFu, minR, off));
        maxR  = max(maxR, __shfl_xor_sync(0xFFFFFFFFu, maxR, off));
        minC  = min(minC, __shfl_xor_sync(0xFFFFFFFFu, minC, off));
        maxC  = max(maxC, __shfl_xor_sync(0xFFFFFFFFu, maxC, off));
    }

    // ---- cross-warp reduction via smem (8 warps) ----
    __shared__ float s_seg[8];
    __shared__ int   s_mnR[8], s_mxR[8], s_mnC[8], s_mxC[8];
    const int wid = tid >> 5, lid = tid & 31;
    if (lid == 0) {
        s_seg[wid] = seg;
        s_mnR[wid] = minR; s_mxR[wid] = maxR;
        s_mnC[wid] = minC; s_mxC[wid] = maxC;
    }
    __syncthreads();
    if (tid == 0) {
        float rs = s_seg[0];
        int rmnR = s_mnR[0], rmxR = s_mxR[0], rmnC = s_mnC[0], rmxC = s_mxC[0];
        #pragma unroll
        for (int w = 1; w < 8; ++w) {
            rs   += s_seg[w];
            rmnR  = min(rmnR, s_mnR[w]); rmxR = max(rmxR, s_mxR[w]);
            rmnC  = min(rmnC, s_mnC[w]); rmxC = max(rmxC, s_mxC[w]);
        }
        g_seg[blk] = rs;
        g_box[blk] = make_int4(rmnR, rmxR, rmnC, rmxC);
    }

    // ---- last-block-finishes tail ----
    __shared__ bool s_isLast;
    __threadfence();
    if (tid == 0) {
        unsigned int c = atomicAdd(&g_count, 1u);
        s_isLast = (c == NBLOCKS - 1);
    }
    __syncthreads();
    if (!s_isLast) return;

    // Tail: thread s handles slice s (256 threads)
    const int s = tid;
    float segT = 0.0f;
    int mnR = INT_MAX, mxR = -1, mnC = INT_MAX, mxC = -1;
    #pragma unroll
    for (int p = 0; p < SPLIT; ++p) {
        int idx = s * SPLIT + p;
        segT += __ldcg(&g_seg[idx]);
        int4 b = __ldcg(&g_box[idx]);
        mnR = min(mnR, b.x); mxR = max(mxR, b.y);
        mnC = min(mnC, b.z); mxC = max(mxC, b.w);
    }

    float bx, by, bw, bh;
    if (mxR < 0) {                       // empty mask
        bx = 0.0f; by = 0.0f; bw = 256.0f; bh = 256.0f;
    } else {
        bx = (float)mnC; by = (float)mnR;
        bw = (float)(mxC - mnC); bh = (float)(mxR - mnR);
    }

    float pred[4] = {bx, by, bw, bh};
    float l = 0.0f;
    #pragma unroll
    for (int j = 0; j < 4; ++j) {
        float d  = pred[j] - tgt[s * 4 + j];
        float ad = fabsf(d);
        l += (ad < 1.0f) ? 0.5f * d * d : ad - 0.5f;
    }

    // reduce 256 lanes: warp shuffle + smem
    #pragma unroll
    for (int off = 16; off > 0; off >>= 1) {
        segT += __shfl_xor_sync(0xFFFFFFFFu, segT, off);
        l    += __shfl_xor_sync(0xFFFFFFFFu, l,    off);
    }
    __shared__ float t_seg[8], t_box[8];
    const int wid2 = tid >> 5, lid2 = tid & 31;
    if (lid2 == 0) { t_seg[wid2] = segT; t_box[wid2] = l; }
    __syncthreads();
    if (tid == 0) {
        float fs = 0.0f, fb = 0.0f;
        #pragma unroll
        for (int w = 0; w < 8; ++w) { fs += t_seg[w]; fb += t_box[w]; }
        out[0] = fs / TOTAL_ELEMS;
        out[1] = fb / NBOX_ELEMS;
        g_count = 0;                     // reset for next graph replay
    }
}

extern "C" void kernel_launch(void* const* d_in, const int* in_sizes, int n_in,
                              void* d_out, int out_size)
{
    const float4* x4 = (const float4*)d_in[0];   // model_output
    const float4* t4 = (const float4*)d_in[1];   // target_masks
    const float*  tb = (const float*)d_in[2];    // target_bboxes
    float* out = (float*)d_out;

    fused_kernel<<<NBLOCKS, THREADS>>>(x4, t4, tb, out);
}